// round 14
// baseline (speedup 1.0000x reference)
#include <cuda_runtime.h>
#include <cuda_bf16.h>
#include <math.h>
#include <stdint.h>

// Problem constants: B=16, C=256, H=W=64, M=512
#define NROWS 65536
#define CDIM  256
#define MDIM  512
#define HWDIM 4096

// ---------------- scratch (device globals; no allocation) ----------------
__device__ __nv_bfloat16 g_qn_hi[NROWS * CDIM];
__device__ __nv_bfloat16 g_qn_lo[NROWS * CDIM];
__device__ __nv_bfloat16 g_E_hi[(size_t)NROWS * MDIM];
__device__ __nv_bfloat16 g_E_lo[(size_t)NROWS * MDIM];
__device__ __nv_bfloat16 g_mem_hi[MDIM * CDIM];
__device__ __nv_bfloat16 g_mem_lo[MDIM * CDIM];
__device__ __nv_bfloat16 g_w1_hi[CDIM * CDIM];
__device__ __nv_bfloat16 g_w1_lo[CDIM * CDIM];
__device__ __nv_bfloat16 g_p_hi[CDIM * MDIM];      // P^T[o][m] = sum_c mem[m,c]*W2[o,c]
__device__ __nv_bfloat16 g_p_lo[CDIM * MDIM];
__device__ float g_mTf[CDIM * MDIM];
__device__ float g_yraw[NROWS * CDIM];
__device__ float g_rowpart[4][NROWS];
__device__ float g_rinv[NROWS];
__device__ float g_cp[512 * MDIM];                 // col-sum partials per n-block (512 blocks)
__device__ float g_cinv[MDIM];
__device__ float g_sp[512 * CDIM];                 // BN sum partials
__device__ float g_sp2[512 * CDIM];
__device__ float g_mean[256];
__device__ float g_rstd[256];

// ---------------- helpers ----------------
__device__ __forceinline__ uint32_t s2u(const void* p) {
    uint32_t a;
    asm("{ .reg .u64 t; cvta.to.shared.u64 t, %1; cvt.u32.u64 %0, t; }" : "=r"(a) : "l"(p));
    return a;
}
__device__ __forceinline__ void cp16(uint32_t s, const void* g) {
    asm volatile("cp.async.ca.shared.global [%0], [%1], 16;" :: "r"(s), "l"(g));
}
__device__ __forceinline__ void ldsm4(uint32_t* r, uint32_t addr) {
    asm volatile("ldmatrix.sync.aligned.m8n8.x4.shared.b16 {%0,%1,%2,%3}, [%4];"
                 : "=r"(r[0]), "=r"(r[1]), "=r"(r[2]), "=r"(r[3]) : "r"(addr));
}
__device__ __forceinline__ void mma_bf(float* d, const uint32_t* a, const uint32_t* b) {
    asm volatile(
        "mma.sync.aligned.m16n8k16.row.col.f32.bf16.bf16.f32 "
        "{%0,%1,%2,%3}, {%4,%5,%6,%7}, {%8,%9}, {%0,%1,%2,%3};"
        : "+f"(d[0]), "+f"(d[1]), "+f"(d[2]), "+f"(d[3])
        : "r"(a[0]), "r"(a[1]), "r"(a[2]), "r"(a[3]), "r"(b[0]), "r"(b[1]));
}
__device__ __forceinline__ uint32_t pack_bf2(__nv_bfloat16 a, __nv_bfloat16 b) {
    return ((uint32_t)__bfloat16_as_ushort(b) << 16) | (uint32_t)__bfloat16_as_ushort(a);
}
__device__ __forceinline__ void split_bf(float v, __nv_bfloat16& h, __nv_bfloat16& l) {
    h = __float2bfloat16(v);
    l = __float2bfloat16(v - __bfloat162float(h));
}

// ---------------- K1: channel-normalize + transpose, write bf16 hi/lo ----------------
__global__ void k_norm(const float* __restrict__ q) {
    __shared__ float s[256][33];
    __shared__ float red[8][32];
    __shared__ float invs[32];
    int n0 = blockIdx.x * 32;
    int b  = n0 >> 12;
    int hw0 = n0 & 4095;
    const float* base = q + (size_t)b * CDIM * HWDIM + hw0;
    for (int idx = threadIdx.x; idx < 256 * 32; idx += 256) {
        int c = idx >> 5, j = idx & 31;
        s[c][j] = base[c * HWDIM + j];
    }
    __syncthreads();
    int j = threadIdx.x & 31, g = threadIdx.x >> 5;
    float p = 0.f;
    #pragma unroll 8
    for (int c = g; c < 256; c += 8) { float v = s[c][j]; p += v * v; }
    red[g][j] = p;
    __syncthreads();
    if (threadIdx.x < 32) {
        float t = 0.f;
        #pragma unroll
        for (int gg = 0; gg < 8; gg++) t += red[gg][threadIdx.x];
        invs[threadIdx.x] = 1.0f / fmaxf(sqrtf(t), 1e-12f);
    }
    __syncthreads();
    for (int idx = threadIdx.x; idx < 256 * 32; idx += 256) {
        int jj = idx >> 8, c = idx & 255;
        float v = s[c][jj] * invs[jj];
        __nv_bfloat16 h, l; split_bf(v, h, l);
        size_t off = (size_t)(n0 + jj) * 256 + c;
        g_qn_hi[off] = h;
        g_qn_lo[off] = l;
    }
}

// ---------------- prep: mem split + fp32 transpose; W1 split ----------------
__global__ void k_prep(const float* __restrict__ mem, const float* __restrict__ w) {
    int i = blockIdx.x * 256 + threadIdx.x;   // 131072
    float v = mem[i];
    __nv_bfloat16 h, l; split_bf(v, h, l);
    g_mem_hi[i] = h; g_mem_lo[i] = l;
    int m = i >> 8, c = i & 255;
    g_mTf[c * 512 + m] = v;
    float wv = w[i];
    int o = i >> 9, k = i & 511;
    if (k < 256) {
        __nv_bfloat16 wh, wl; split_bf(wv, wh, wl);
        g_w1_hi[o * 256 + k] = wh;
        g_w1_lo[o * 256 + k] = wl;
    }
}

// ---------------- P^T[o][m] = sum_c mem[m,c] * conv_w[o, 256+c] (fp32) ----------------
__global__ void k_compP(const float* __restrict__ w) {
    __shared__ float sw[8][256];
    int m = blockIdx.x * 256 + threadIdx.x;   // grid.x = 2
    int o0 = blockIdx.y * 8;                  // grid.y = 32
    for (int idx = threadIdx.x; idx < 8 * 256; idx += 256) {
        int jj = idx >> 8, c = idx & 255;
        sw[jj][c] = w[(size_t)(o0 + jj) * 512 + 256 + c];
    }
    __syncthreads();
    float acc[8] = {};
    for (int c = 0; c < 256; c++) {
        float v = g_mTf[c * 512 + m];
        #pragma unroll
        for (int jj = 0; jj < 8; jj++) acc[jj] += v * sw[jj][c];
    }
    #pragma unroll
    for (int jj = 0; jj < 8; jj++) {
        __nv_bfloat16 h, l; split_bf(acc[jj], h, l);
        g_p_hi[(o0 + jj) * 512 + m] = h;
        g_p_lo[(o0 + jj) * 512 + m] = l;
    }
}

// ---------------- mma.sync bf16x3 GEMM, 512 threads, CTA 128x128, warp 32x32 ----------------
// MODE 1: E = exp(qn @ mem^T)  [N,512], K=256, grid(4,512); fused row+col partials
// MODE 2: y = rinv*(E @ P^T) + qn @ W1^T, K=768, grid(2,512); BOHW store + BN partials
#define LDA 40                        // halves per smem row (32 + 8 pad)
#define PLANE_B2 (128 * LDA * 2)      // 10240 bytes
#define A_HI 0
#define A_LO PLANE_B2
#define B_HI (2 * PLANE_B2)
#define B_LO (3 * PLANE_B2)
#define STAGE_B (4 * PLANE_B2)        // 40960
#define NSTAGES 3
#define SMEM_DYN (NSTAGES * STAGE_B)  // 122880

template <int MODE>
__global__ __launch_bounds__(512, 1) void k_gemm_mma() {
    extern __shared__ __align__(16) char smem_raw[];
    uint32_t smem_u = s2u(smem_raw);
    float* Ts   = (float*)smem_raw;               // epilogue staging 128x132 (67584 B)
    float* red1 = (float*)smem_raw + 16896;       // 512 floats
    float* red2 = (float*)smem_raw + 17408;       // 512 floats

    int tid = threadIdx.x, lane = tid & 31, wid = tid >> 5;
    int warp_m = wid & 3, warp_n = wid >> 2;      // 4 x 4 warps, warp tile 32x32
    int n0 = blockIdx.y * 128;
    int m0 = blockIdx.x * 128;
    const int NITER = (MODE == 1) ? 8 : 24;
    int gID = lane >> 2, t4 = lane & 3;

    float acc[2][4][4];
    #pragma unroll
    for (int a = 0; a < 2; a++)
        #pragma unroll
        for (int b = 0; b < 4; b++)
            #pragma unroll
            for (int c = 0; c < 4; c++) acc[a][b][c] = 0.f;

    auto issue = [&](int kc) {
        const __nv_bfloat16 *Ah, *Al, *Bh, *Bl;
        int aS, bS, ak0, bk0;
        if (MODE == 1) {
            Ah = g_qn_hi; Al = g_qn_lo; aS = 256; ak0 = kc * 32;
            Bh = g_mem_hi; Bl = g_mem_lo; bS = 256; bk0 = kc * 32;
        } else if (kc < 16) {
            Ah = g_E_hi; Al = g_E_lo; aS = 512; ak0 = kc * 32;
            Bh = g_p_hi; Bl = g_p_lo; bS = 512; bk0 = kc * 32;
        } else {
            Ah = g_qn_hi; Al = g_qn_lo; aS = 256; ak0 = (kc - 16) * 32;
            Bh = g_w1_hi; Bl = g_w1_lo; bS = 256; bk0 = (kc - 16) * 32;
        }
        uint32_t sb = smem_u + (kc % NSTAGES) * STAGE_B;
        int r = tid >> 2, seg = tid & 3;          // 128 rows x 4 segs = 512 slots
        uint32_t so = sb + (uint32_t)(r * LDA + seg * 8) * 2;
        size_t aoff = (size_t)(n0 + r) * aS + ak0 + seg * 8;
        size_t boff = (size_t)(m0 + r) * bS + bk0 + seg * 8;
        cp16(so + A_HI, Ah + aoff);
        cp16(so + A_LO, Al + aoff);
        cp16(so + B_HI, Bh + boff);
        cp16(so + B_LO, Bl + boff);
        asm volatile("cp.async.commit_group;" ::: "memory");
    };

    issue(0);
    issue(1);
    for (int kc = 0; kc < NITER; kc++) {
        if (kc < NITER - 1) {
            asm volatile("cp.async.wait_group 1;" ::: "memory");
        } else {
            asm volatile("cp.async.wait_group 0;" ::: "memory");
        }
        __syncthreads();
        if (kc + 2 < NITER) issue(kc + 2);

        uint32_t sbase = smem_u + (kc % NSTAGES) * STAGE_B;
        #pragma unroll
        for (int ki = 0; ki < 2; ki++) {
            uint32_t a_h[2][4], a_l[2][4];
            #pragma unroll
            for (int mi = 0; mi < 2; mi++) {
                int row = warp_m * 32 + mi * 16 + (lane & 15);
                int col = ki * 16 + (lane >> 4) * 8;
                uint32_t ad = sbase + A_HI + (uint32_t)(row * LDA + col) * 2;
                ldsm4(a_h[mi], ad);
                ldsm4(a_l[mi], ad + PLANE_B2);
            }
            #pragma unroll
            for (int ng = 0; ng < 2; ng++) {
                int nrow = warp_n * 32 + ng * 16 + (lane & 7) + ((lane >> 4) & 1) * 8;
                int ncol = ki * 16 + ((lane >> 3) & 1) * 8;
                uint32_t bd = sbase + B_HI + (uint32_t)(nrow * LDA + ncol) * 2;
                uint32_t bh[4], bl[4];
                ldsm4(bh, bd);
                ldsm4(bl, bd + PLANE_B2);
                #pragma unroll
                for (int mi = 0; mi < 2; mi++) {
                    mma_bf(acc[mi][2 * ng],     a_h[mi], bh);
                    mma_bf(acc[mi][2 * ng],     a_h[mi], bl);
                    mma_bf(acc[mi][2 * ng],     a_l[mi], bh);
                    mma_bf(acc[mi][2 * ng + 1], a_h[mi], bh + 2);
                    mma_bf(acc[mi][2 * ng + 1], a_h[mi], bl + 2);
                    mma_bf(acc[mi][2 * ng + 1], a_l[mi], bh + 2);
                }
            }
        }

        if (MODE == 2 && kc == 15) {
            #pragma unroll
            for (int mi = 0; mi < 2; mi++) {
                int r0 = n0 + warp_m * 32 + mi * 16 + gID;
                float rv0 = g_rinv[r0];
                float rv1 = g_rinv[r0 + 8];
                #pragma unroll
                for (int ni = 0; ni < 4; ni++) {
                    acc[mi][ni][0] *= rv0;
                    acc[mi][ni][1] *= rv0;
                    acc[mi][ni][2] *= rv1;
                    acc[mi][ni][3] *= rv1;
                }
            }
        }
    }

    __syncthreads();   // mainloop done; smem reusable for staging

    if (MODE == 2) {
        // stage transposed: Ts[o][n], stride 132
        #pragma unroll
        for (int mi = 0; mi < 2; mi++)
            #pragma unroll
            for (int ni = 0; ni < 4; ni++) {
                int r0 = warp_m * 32 + mi * 16 + gID;
                int c  = warp_n * 32 + ni * 8 + t4 * 2;
                Ts[c * 132 + r0]           = acc[mi][ni][0];
                Ts[(c + 1) * 132 + r0]     = acc[mi][ni][1];
                Ts[c * 132 + r0 + 8]       = acc[mi][ni][2];
                Ts[(c + 1) * 132 + r0 + 8] = acc[mi][ni][3];
            }
        __syncthreads();
        int b = n0 >> 12, hw0 = n0 & 4095;
        float* ybase = g_yraw + (size_t)b * (256 * 4096) + hw0;
        #pragma unroll
        for (int p = 0; p < 8; p++) {
            int q = p * 512 + tid;
            int o = q >> 5, seg = q & 31;
            float4 v = *(float4*)&Ts[o * 132 + seg * 4];
            *(float4*)(ybase + (size_t)(m0 + o) * 4096 + seg * 4) = v;
        }
        {
            int o = tid >> 2, q = tid & 3;
            float s = 0.f, s2 = 0.f;
            #pragma unroll 8
            for (int jj = 0; jj < 32; jj++) {
                float v = Ts[o * 132 + q * 32 + jj];
                s += v; s2 += v * v;
            }
            red1[tid] = s; red2[tid] = s2;
        }
        __syncthreads();
        if (tid < 128) {
            g_sp [blockIdx.y * 256 + m0 + tid] =
                red1[4 * tid] + red1[4 * tid + 1] + red1[4 * tid + 2] + red1[4 * tid + 3];
            g_sp2[blockIdx.y * 256 + m0 + tid] =
                red2[4 * tid] + red2[4 * tid + 1] + red2[4 * tid + 2] + red2[4 * tid + 3];
        }
        return;
    }

    // MODE 1: stage exp values row-major Ts[n][c], stride 132
    #pragma unroll
    for (int mi = 0; mi < 2; mi++)
        #pragma unroll
        for (int ni = 0; ni < 4; ni++) {
            int r0 = warp_m * 32 + mi * 16 + gID;
            int c  = warp_n * 32 + ni * 8 + t4 * 2;
            Ts[r0 * 132 + c]           = expf(acc[mi][ni][0]);
            Ts[r0 * 132 + c + 1]       = expf(acc[mi][ni][1]);
            Ts[(r0 + 8) * 132 + c]     = expf(acc[mi][ni][2]);
            Ts[(r0 + 8) * 132 + c + 1] = expf(acc[mi][ni][3]);
        }
    __syncthreads();

    // row partial sums (128 rows x 128 cols)
    {
        int r = tid >> 2, q = tid & 3;
        float s = 0.f;
        #pragma unroll 8
        for (int jj = 0; jj < 32; jj++) s += Ts[r * 132 + q * 32 + jj];
        red1[tid] = s;
    }
    // column partial sums
    {
        int c = tid & 127, rq = tid >> 7;
        float s = 0.f;
        #pragma unroll 8
        for (int rr = 0; rr < 32; rr++) s += Ts[(rq * 32 + rr) * 132 + c];
        red2[tid] = s;
    }
    // pack bf16 hi/lo, coalesced
    #pragma unroll
    for (int p = 0; p < 4; p++) {
        int cid = p * 512 + tid;
        int r = cid >> 4, cc = cid & 15;
        uint32_t hp[4], lp[4];
        #pragma unroll
        for (int jj = 0; jj < 4; jj++) {
            float v0 = Ts[r * 132 + cc * 8 + 2 * jj];
            float v1 = Ts[r * 132 + cc * 8 + 2 * jj + 1];
            __nv_bfloat16 h0, l0, h1, l1;
            split_bf(v0, h0, l0);
            split_bf(v1, h1, l1);
            hp[jj] = pack_bf2(h0, h1);
            lp[jj] = pack_bf2(l0, l1);
        }
        size_t off = (size_t)(n0 + r) * 512 + m0 + cc * 8;
        *(uint4*)(g_E_hi + off) = *(uint4*)hp;
        *(uint4*)(g_E_lo + off) = *(uint4*)lp;
    }
    __syncthreads();
    if (tid < 128) {
        g_rowpart[blockIdx.x][n0 + tid] =
            red1[4 * tid] + red1[4 * tid + 1] + red1[4 * tid + 2] + red1[4 * tid + 3];
        g_cp[blockIdx.y * 512 + m0 + tid] =
            red2[tid] + red2[tid + 128] + red2[tid + 256] + red2[tid + 384];
    }
}

// ---------------- rinv from row partials ----------------
__global__ void k_rinv() {
    int n = blockIdx.x * 256 + threadIdx.x;
    g_rinv[n] = 1.0f / (g_rowpart[0][n] + g_rowpart[1][n] + g_rowpart[2][n] + g_rowpart[3][n]);
}

// ---------------- cinv from column partials ----------------
__global__ void k_colfin() {
    int m = threadIdx.x;   // 512 threads, 1 block
    float s = 0.f;
    #pragma unroll 8
    for (int y = 0; y < 512; y++) s += g_cp[y * 512 + m];
    g_cinv[m] = 1.0f / s;
}

// ---------------- write both softmax outputs ----------------
__global__ void k_soft(float* __restrict__ ssq, float* __restrict__ ssm) {
    size_t idx = (size_t)blockIdx.x * 256 + threadIdx.x;
    size_t e0 = idx * 8;
    int n = (int)(e0 >> 9);
    int m = (int)(e0 & 511);
    uint4 hv = *(const uint4*)(g_E_hi + e0);
    uint4 lv = *(const uint4*)(g_E_lo + e0);
    float rv = g_rinv[n];
    const __nv_bfloat162* hp = (const __nv_bfloat162*)&hv;
    const __nv_bfloat162* lp = (const __nv_bfloat162*)&lv;
    float eo[8];
    #pragma unroll
    for (int i = 0; i < 4; i++) {
        float2 h2 = __bfloat1622float2(hp[i]);
        float2 l2 = __bfloat1622float2(lp[i]);
        eo[2 * i]     = h2.x + l2.x;
        eo[2 * i + 1] = h2.y + l2.y;
    }
    float4 sm0 = make_float4(eo[0] * rv, eo[1] * rv, eo[2] * rv, eo[3] * rv);
    float4 sm1 = make_float4(eo[4] * rv, eo[5] * rv, eo[6] * rv, eo[7] * rv);
    float4 sq0 = make_float4(eo[0] * g_cinv[m], eo[1] * g_cinv[m + 1],
                             eo[2] * g_cinv[m + 2], eo[3] * g_cinv[m + 3]);
    float4 sq1 = make_float4(eo[4] * g_cinv[m + 4], eo[5] * g_cinv[m + 5],
                             eo[6] * g_cinv[m + 6], eo[7] * g_cinv[m + 7]);
    *(float4*)(ssm + e0) = sm0;
    *(float4*)(ssm + e0 + 4) = sm1;
    *(float4*)(ssq + e0) = sq0;
    *(float4*)(ssq + e0 + 4) = sq1;
}

// ---------------- BN statistics finalize from partials ----------------
__global__ void k_statfin() {
    int o = threadIdx.x;   // 256 threads, 1 block
    float s = 0.f, s2 = 0.f;
    #pragma unroll 8
    for (int y = 0; y < 512; y++) {
        s  += g_sp [y * 256 + o];
        s2 += g_sp2[y * 256 + o];
    }
    float mean = s * (1.0f / 65536.0f);
    float var  = s2 * (1.0f / 65536.0f) - mean * mean;
    g_mean[o] = mean;
    g_rstd[o] = rsqrtf(var + 1e-5f);
}

// ---------------- BN affine + ReLU ----------------
__global__ void k_bn(const float* __restrict__ gamma, const float* __restrict__ beta,
                     float* __restrict__ yout) {
    int idx = blockIdx.x * blockDim.x + threadIdx.x;
    size_t e0 = (size_t)idx * 4;
    int o = (int)((e0 >> 12) & 255);
    float4 v = *(const float4*)(g_yraw + e0);
    float sc = g_rstd[o] * gamma[o];
    float sh = beta[o] - g_mean[o] * sc;
    float4 r = make_float4(fmaxf(v.x * sc + sh, 0.f), fmaxf(v.y * sc + sh, 0.f),
                           fmaxf(v.z * sc + sh, 0.f), fmaxf(v.w * sc + sh, 0.f));
    *(float4*)(yout + e0) = r;
}

// ---------------- launch ----------------
extern "C" void kernel_launch(void* const* d_in, const int* in_sizes, int n_in,
                              void* d_out, int out_size) {
    const float* query = (const float*)d_in[0];
    const float* mem   = (const float*)d_in[1];
    const float* convw = (const float*)d_in[2];
    const float* gamma = (const float*)d_in[3];
    const float* beta  = (const float*)d_in[4];

    float* out = (float*)d_out;
    float* y_out   = out;
    float* ssq_out = out + 16777216;
    float* ssm_out = out + 16777216 + 33554432;

    cudaFuncSetAttribute(k_gemm_mma<1>, cudaFuncAttributeMaxDynamicSharedMemorySize, SMEM_DYN);
    cudaFuncSetAttribute(k_gemm_mma<2>, cudaFuncAttributeMaxDynamicSharedMemorySize, SMEM_DYN);

    k_norm   <<<2048, 256>>>(query);
    k_prep   <<<512, 256>>>(mem, convw);
    k_compP  <<<dim3(2, 32), 256>>>(convw);
    k_gemm_mma<1><<<dim3(4, 512), 512, SMEM_DYN>>>();
    k_rinv   <<<256, 256>>>();
    k_colfin <<<1, 512>>>();
    k_soft   <<<16384, 256>>>(ssq_out, ssm_out);
    k_gemm_mma<2><<<dim3(2, 512), 512, SMEM_DYN>>>();
    k_statfin<<<1, 256>>>();
    k_bn     <<<16384, 256>>>(gamma, beta, y_out);
}

// round 15
// speedup vs baseline: 1.0035x; 1.0035x over previous
#include <cuda_runtime.h>
#include <cuda_bf16.h>
#include <math.h>
#include <stdint.h>

// Problem constants: B=16, C=256, H=W=64, M=512
#define NROWS 65536
#define CDIM  256
#define MDIM  512
#define HWDIM 4096

// ---------------- scratch (device globals; no allocation) ----------------
__device__ __nv_bfloat16 g_qn_hi[NROWS * CDIM];
__device__ __nv_bfloat16 g_qn_lo[NROWS * CDIM];
__device__ __nv_bfloat16 g_E_hi[(size_t)NROWS * MDIM];
__device__ __nv_bfloat16 g_E_lo[(size_t)NROWS * MDIM];
__device__ __nv_bfloat16 g_mem_hi[MDIM * CDIM];
__device__ __nv_bfloat16 g_mem_lo[MDIM * CDIM];
__device__ __nv_bfloat16 g_w1_hi[CDIM * CDIM];
__device__ __nv_bfloat16 g_w1_lo[CDIM * CDIM];
__device__ __nv_bfloat16 g_p_hi[CDIM * MDIM];      // P^T[o][m] = sum_c mem[m,c]*W2[o,c]
__device__ __nv_bfloat16 g_p_lo[CDIM * MDIM];
__device__ float g_mTf[CDIM * MDIM];
__device__ float g_yraw[NROWS * CDIM];
__device__ float g_rowpart[4][NROWS];
__device__ float g_rinv[NROWS];
__device__ float g_cp[512 * MDIM];                 // col-sum partials per n-block
__device__ float g_cinv[MDIM];
__device__ float g_sp[512 * CDIM];                 // BN sum partials
__device__ float g_sp2[512 * CDIM];
__device__ float g_mean[256];
__device__ float g_rstd[256];

// ---------------- helpers ----------------
__device__ __forceinline__ uint32_t s2u(const void* p) {
    uint32_t a;
    asm("{ .reg .u64 t; cvta.to.shared.u64 t, %1; cvt.u32.u64 %0, t; }" : "=r"(a) : "l"(p));
    return a;
}
__device__ __forceinline__ void cp16(uint32_t s, const void* g) {
    asm volatile("cp.async.ca.shared.global [%0], [%1], 16;" :: "r"(s), "l"(g));
}
__device__ __forceinline__ void ldsm4(uint32_t* r, uint32_t addr) {
    asm volatile("ldmatrix.sync.aligned.m8n8.x4.shared.b16 {%0,%1,%2,%3}, [%4];"
                 : "=r"(r[0]), "=r"(r[1]), "=r"(r[2]), "=r"(r[3]) : "r"(addr));
}
__device__ __forceinline__ void mma_bf(float* d, const uint32_t* a, const uint32_t* b) {
    asm volatile(
        "mma.sync.aligned.m16n8k16.row.col.f32.bf16.bf16.f32 "
        "{%0,%1,%2,%3}, {%4,%5,%6,%7}, {%8,%9}, {%0,%1,%2,%3};"
        : "+f"(d[0]), "+f"(d[1]), "+f"(d[2]), "+f"(d[3])
        : "r"(a[0]), "r"(a[1]), "r"(a[2]), "r"(a[3]), "r"(b[0]), "r"(b[1]));
}
__device__ __forceinline__ uint32_t pack_bf2(__nv_bfloat16 a, __nv_bfloat16 b) {
    return ((uint32_t)__bfloat16_as_ushort(b) << 16) | (uint32_t)__bfloat16_as_ushort(a);
}
__device__ __forceinline__ void split_bf(float v, __nv_bfloat16& h, __nv_bfloat16& l) {
    h = __float2bfloat16(v);
    l = __float2bfloat16(v - __bfloat162float(h));
}

// ---------------- K1: channel-normalize + transpose, write bf16 hi/lo ----------------
__global__ void k_norm(const float* __restrict__ q) {
    __shared__ float s[256][33];
    __shared__ float red[8][32];
    __shared__ float invs[32];
    int n0 = blockIdx.x * 32;
    int b  = n0 >> 12;
    int hw0 = n0 & 4095;
    const float* base = q + (size_t)b * CDIM * HWDIM + hw0;
    for (int idx = threadIdx.x; idx < 256 * 32; idx += 256) {
        int c = idx >> 5, j = idx & 31;
        s[c][j] = base[c * HWDIM + j];
    }
    __syncthreads();
    int j = threadIdx.x & 31, g = threadIdx.x >> 5;
    float p = 0.f;
    #pragma unroll 8
    for (int c = g; c < 256; c += 8) { float v = s[c][j]; p += v * v; }
    red[g][j] = p;
    __syncthreads();
    if (threadIdx.x < 32) {
        float t = 0.f;
        #pragma unroll
        for (int gg = 0; gg < 8; gg++) t += red[gg][threadIdx.x];
        invs[threadIdx.x] = 1.0f / fmaxf(sqrtf(t), 1e-12f);
    }
    __syncthreads();
    for (int idx = threadIdx.x; idx < 256 * 32; idx += 256) {
        int jj = idx >> 8, c = idx & 255;
        float v = s[c][jj] * invs[jj];
        __nv_bfloat16 h, l; split_bf(v, h, l);
        size_t off = (size_t)(n0 + jj) * 256 + c;
        g_qn_hi[off] = h;
        g_qn_lo[off] = l;
    }
}

// ---------------- prep: mem split + fp32 transpose; W1 split ----------------
__global__ void k_prep(const float* __restrict__ mem, const float* __restrict__ w) {
    int i = blockIdx.x * 256 + threadIdx.x;   // 131072
    float v = mem[i];
    __nv_bfloat16 h, l; split_bf(v, h, l);
    g_mem_hi[i] = h; g_mem_lo[i] = l;
    int m = i >> 8, c = i & 255;
    g_mTf[c * 512 + m] = v;
    float wv = w[i];
    int o = i >> 9, k = i & 511;
    if (k < 256) {
        __nv_bfloat16 wh, wl; split_bf(wv, wh, wl);
        g_w1_hi[o * 256 + k] = wh;
        g_w1_lo[o * 256 + k] = wl;
    }
}

// ---------------- P^T[o][m] = sum_c mem[m,c] * conv_w[o, 256+c] (fp32) ----------------
__global__ void k_compP(const float* __restrict__ w) {
    __shared__ float sw[8][256];
    int m = blockIdx.x * 256 + threadIdx.x;   // grid.x = 2
    int o0 = blockIdx.y * 8;                  // grid.y = 32
    for (int idx = threadIdx.x; idx < 8 * 256; idx += 256) {
        int jj = idx >> 8, c = idx & 255;
        sw[jj][c] = w[(size_t)(o0 + jj) * 512 + 256 + c];
    }
    __syncthreads();
    float acc[8] = {};
    for (int c = 0; c < 256; c++) {
        float v = g_mTf[c * 512 + m];
        #pragma unroll
        for (int jj = 0; jj < 8; jj++) acc[jj] += v * sw[jj][c];
    }
    #pragma unroll
    for (int jj = 0; jj < 8; jj++) {
        __nv_bfloat16 h, l; split_bf(acc[jj], h, l);
        g_p_hi[(o0 + jj) * 512 + m] = h;
        g_p_lo[(o0 + jj) * 512 + m] = l;
    }
}

// ---------------- GEMM1 (R14-proven): E = exp(qn @ mem^T), 512 thr, CTA 128x128 ----------------
#define LDA 40
#define PLANE_B2 (128 * LDA * 2)      // 10240
#define A_HI 0
#define A_LO PLANE_B2
#define B_HI (2 * PLANE_B2)
#define B_LO (3 * PLANE_B2)
#define STAGE_B (4 * PLANE_B2)        // 40960
#define NSTAGES 3
#define SMEM1_DYN (NSTAGES * STAGE_B) // 122880

__global__ __launch_bounds__(512, 1) void k_gemm1() {
    extern __shared__ __align__(16) char smem_raw[];
    uint32_t smem_u = s2u(smem_raw);
    float* Ts   = (float*)smem_raw;               // 128x132
    float* red1 = (float*)smem_raw + 16896;
    float* red2 = (float*)smem_raw + 17408;

    int tid = threadIdx.x, lane = tid & 31, wid = tid >> 5;
    int warp_m = wid & 3, warp_n = wid >> 2;      // 4x4, warp tile 32x32
    int n0 = blockIdx.y * 128;
    int m0 = blockIdx.x * 128;
    int gID = lane >> 2, t4 = lane & 3;

    float acc[2][4][4];
    #pragma unroll
    for (int a = 0; a < 2; a++)
        #pragma unroll
        for (int b = 0; b < 4; b++)
            #pragma unroll
            for (int c = 0; c < 4; c++) acc[a][b][c] = 0.f;

    auto issue = [&](int kc) {
        uint32_t sb = smem_u + (kc % NSTAGES) * STAGE_B;
        int r = tid >> 2, seg = tid & 3;
        uint32_t so = sb + (uint32_t)(r * LDA + seg * 8) * 2;
        size_t aoff = (size_t)(n0 + r) * 256 + kc * 32 + seg * 8;
        size_t boff = (size_t)(m0 + r) * 256 + kc * 32 + seg * 8;
        cp16(so + A_HI, g_qn_hi + aoff);
        cp16(so + A_LO, g_qn_lo + aoff);
        cp16(so + B_HI, g_mem_hi + boff);
        cp16(so + B_LO, g_mem_lo + boff);
        asm volatile("cp.async.commit_group;" ::: "memory");
    };

    issue(0);
    issue(1);
    for (int kc = 0; kc < 8; kc++) {
        if (kc < 7) {
            asm volatile("cp.async.wait_group 1;" ::: "memory");
        } else {
            asm volatile("cp.async.wait_group 0;" ::: "memory");
        }
        __syncthreads();
        if (kc + 2 < 8) issue(kc + 2);

        uint32_t sbase = smem_u + (kc % NSTAGES) * STAGE_B;
        #pragma unroll
        for (int ki = 0; ki < 2; ki++) {
            uint32_t a_h[2][4], a_l[2][4];
            #pragma unroll
            for (int mi = 0; mi < 2; mi++) {
                int row = warp_m * 32 + mi * 16 + (lane & 15);
                int col = ki * 16 + (lane >> 4) * 8;
                uint32_t ad = sbase + A_HI + (uint32_t)(row * LDA + col) * 2;
                ldsm4(a_h[mi], ad);
                ldsm4(a_l[mi], ad + PLANE_B2);
            }
            #pragma unroll
            for (int ng = 0; ng < 2; ng++) {
                int nrow = warp_n * 32 + ng * 16 + (lane & 7) + ((lane >> 4) & 1) * 8;
                int ncol = ki * 16 + ((lane >> 3) & 1) * 8;
                uint32_t bd = sbase + B_HI + (uint32_t)(nrow * LDA + ncol) * 2;
                uint32_t bh[4], bl[4];
                ldsm4(bh, bd);
                ldsm4(bl, bd + PLANE_B2);
                #pragma unroll
                for (int mi = 0; mi < 2; mi++) {
                    mma_bf(acc[mi][2 * ng],     a_h[mi], bh);
                    mma_bf(acc[mi][2 * ng],     a_h[mi], bl);
                    mma_bf(acc[mi][2 * ng],     a_l[mi], bh);
                    mma_bf(acc[mi][2 * ng + 1], a_h[mi], bh + 2);
                    mma_bf(acc[mi][2 * ng + 1], a_h[mi], bl + 2);
                    mma_bf(acc[mi][2 * ng + 1], a_l[mi], bh + 2);
                }
            }
        }
    }

    __syncthreads();

    // epilogue: exp, stage, reductions, bf16 pack
    #pragma unroll
    for (int mi = 0; mi < 2; mi++)
        #pragma unroll
        for (int ni = 0; ni < 4; ni++) {
            int r0 = warp_m * 32 + mi * 16 + gID;
            int c  = warp_n * 32 + ni * 8 + t4 * 2;
            Ts[r0 * 132 + c]           = expf(acc[mi][ni][0]);
            Ts[r0 * 132 + c + 1]       = expf(acc[mi][ni][1]);
            Ts[(r0 + 8) * 132 + c]     = expf(acc[mi][ni][2]);
            Ts[(r0 + 8) * 132 + c + 1] = expf(acc[mi][ni][3]);
        }
    __syncthreads();
    {
        int r = tid >> 2, q = tid & 3;
        float s = 0.f;
        #pragma unroll 8
        for (int jj = 0; jj < 32; jj++) s += Ts[r * 132 + q * 32 + jj];
        red1[tid] = s;
    }
    {
        int c = tid & 127, rq = tid >> 7;
        float s = 0.f;
        #pragma unroll 8
        for (int rr = 0; rr < 32; rr++) s += Ts[(rq * 32 + rr) * 132 + c];
        red2[tid] = s;
    }
    #pragma unroll
    for (int p = 0; p < 4; p++) {
        int cid = p * 512 + tid;
        int r = cid >> 4, cc = cid & 15;
        uint32_t hp[4], lp[4];
        #pragma unroll
        for (int jj = 0; jj < 4; jj++) {
            float v0 = Ts[r * 132 + cc * 8 + 2 * jj];
            float v1 = Ts[r * 132 + cc * 8 + 2 * jj + 1];
            __nv_bfloat16 h0, l0, h1, l1;
            split_bf(v0, h0, l0);
            split_bf(v1, h1, l1);
            hp[jj] = pack_bf2(h0, h1);
            lp[jj] = pack_bf2(l0, l1);
        }
        size_t off = (size_t)(n0 + r) * 512 + m0 + cc * 8;
        *(uint4*)(g_E_hi + off) = *(uint4*)hp;
        *(uint4*)(g_E_lo + off) = *(uint4*)lp;
    }
    __syncthreads();
    if (tid < 128) {
        g_rowpart[blockIdx.x][n0 + tid] =
            red1[4 * tid] + red1[4 * tid + 1] + red1[4 * tid + 2] + red1[4 * tid + 3];
        g_cp[blockIdx.y * 512 + m0 + tid] =
            red2[tid] + red2[tid + 128] + red2[tid + 256] + red2[tid + 384];
    }
}

// ---------------- GEMM2 fused: y = rinv*(E@P^T) + qn@W1^T  AND  ssm/ssq writes ----------------
// grid (1, 512), 512 threads, output tile 128 rows x 256 outs, warp tile 32x64.
#define A2_PLANE (128 * LDA * 2)      // 10240
#define B2_PLANE (256 * LDA * 2)      // 20480
#define A2_HI 0
#define A2_LO A2_PLANE
#define B2_HI (2 * A2_PLANE)
#define B2_LO (2 * A2_PLANE + B2_PLANE)
#define STAGE2_B (2 * A2_PLANE + 2 * B2_PLANE)   // 61440
#define SMEM2_DYN (NSTAGES * STAGE2_B)           // 184320

__global__ __launch_bounds__(512, 1) void k_gemm2(float* __restrict__ ssq,
                                                  float* __restrict__ ssm) {
    extern __shared__ __align__(16) char smem_raw[];
    uint32_t smem_u = s2u(smem_raw);
    float* Ts   = (float*)smem_raw;               // 256x132 staging = 135168 B
    float* red1 = (float*)smem_raw + 33792;       // 512 floats
    float* red2 = (float*)smem_raw + 34304;

    int tid = threadIdx.x, lane = tid & 31, wid = tid >> 5;
    int warp_m = wid & 3, warp_n = wid >> 2;      // 4x4: warp tile 32 rows x 64 outs
    int n0 = blockIdx.y * 128;
    int gID = lane >> 2, t4 = lane & 3;
    float rinv_r = g_rinv[n0 + (tid >> 2)];       // for fused softmax (row tid>>2)

    float acc[2][8][4];
    #pragma unroll
    for (int a = 0; a < 2; a++)
        #pragma unroll
        for (int b = 0; b < 8; b++)
            #pragma unroll
            for (int c = 0; c < 4; c++) acc[a][b][c] = 0.f;

    auto issue = [&](int kc) {
        const __nv_bfloat16 *Ah, *Al, *Bh, *Bl;
        int aS, bS, k0;
        if (kc < 16) {
            Ah = g_E_hi; Al = g_E_lo; aS = 512;
            Bh = g_p_hi; Bl = g_p_lo; bS = 512; k0 = kc * 32;
        } else {
            Ah = g_qn_hi; Al = g_qn_lo; aS = 256;
            Bh = g_w1_hi; Bl = g_w1_lo; bS = 256; k0 = (kc - 16) * 32;
        }
        uint32_t sb = smem_u + (kc % NSTAGES) * STAGE2_B;
        {   // A: 128 rows x 4 segs = 512 slots
            int r = tid >> 2, seg = tid & 3;
            uint32_t so = sb + (uint32_t)(r * LDA + seg * 8) * 2;
            size_t aoff = (size_t)(n0 + r) * aS + k0 + seg * 8;
            cp16(so + A2_HI, Ah + aoff);
            cp16(so + A2_LO, Al + aoff);
        }
        #pragma unroll
        for (int it = 0; it < 2; it++) {   // B: 256 rows x 4 segs = 1024 slots
            int i = tid + it * 512;
            int r = i >> 2, seg = i & 3;
            uint32_t so = sb + (uint32_t)(r * LDA + seg * 8) * 2;
            size_t boff = (size_t)r * bS + k0 + seg * 8;
            cp16(so + B2_HI, Bh + boff);
            cp16(so + B2_LO, Bl + boff);
        }
        asm volatile("cp.async.commit_group;" ::: "memory");
    };

    issue(0);
    issue(1);
    for (int kc = 0; kc < 24; kc++) {
        if (kc < 23) {
            asm volatile("cp.async.wait_group 1;" ::: "memory");
        } else {
            asm volatile("cp.async.wait_group 0;" ::: "memory");
        }
        __syncthreads();
        if (kc + 2 < 24) issue(kc + 2);

        uint32_t sbase = smem_u + (kc % NSTAGES) * STAGE2_B;

        // ---- fused softmax outputs: this chunk's A-tile is E[n0..n0+127][kc*32..+32) ----
        if (kc < 16) {
            int r = tid >> 2, seg = tid & 3;
            uint32_t so = sbase + (uint32_t)(r * LDA + seg * 8) * 2;
            uint4 hv = *(uint4*)(smem_raw + (so - smem_u) + A2_HI);
            uint4 lv = *(uint4*)(smem_raw + (so - smem_u) + A2_LO);
            const __nv_bfloat162* hp = (const __nv_bfloat162*)&hv;
            const __nv_bfloat162* lp = (const __nv_bfloat162*)&lv;
            int mbase = kc * 32 + seg * 8;
            float e[8];
            #pragma unroll
            for (int i = 0; i < 4; i++) {
                float2 h2 = __bfloat1622float2(hp[i]);
                float2 l2 = __bfloat1622float2(lp[i]);
                e[2 * i]     = h2.x + l2.x;
                e[2 * i + 1] = h2.y + l2.y;
            }
            size_t obase = (size_t)(n0 + r) * 512 + mbase;
            float4 sm0 = make_float4(e[0] * rinv_r, e[1] * rinv_r, e[2] * rinv_r, e[3] * rinv_r);
            float4 sm1 = make_float4(e[4] * rinv_r, e[5] * rinv_r, e[6] * rinv_r, e[7] * rinv_r);
            float4 sq0 = make_float4(e[0] * g_cinv[mbase], e[1] * g_cinv[mbase + 1],
                                     e[2] * g_cinv[mbase + 2], e[3] * g_cinv[mbase + 3]);
            float4 sq1 = make_float4(e[4] * g_cinv[mbase + 4], e[5] * g_cinv[mbase + 5],
                                     e[6] * g_cinv[mbase + 6], e[7] * g_cinv[mbase + 7]);
            *(float4*)(ssm + obase)     = sm0;
            *(float4*)(ssm + obase + 4) = sm1;
            *(float4*)(ssq + obase)     = sq0;
            *(float4*)(ssq + obase + 4) = sq1;
        }

        // ---- MMA ----
        #pragma unroll
        for (int ki = 0; ki < 2; ki++) {
            uint32_t a_h[2][4], a_l[2][4];
            #pragma unroll
            for (int mi = 0; mi < 2; mi++) {
                int row = warp_m * 32 + mi * 16 + (lane & 15);
                int col = ki * 16 + (lane >> 4) * 8;
                uint32_t ad = sbase + A2_HI + (uint32_t)(row * LDA + col) * 2;
                ldsm4(a_h[mi], ad);
                ldsm4(a_l[mi], ad + A2_PLANE);
            }
            #pragma unroll
            for (int ng = 0; ng < 4; ng++) {
                int nrow = warp_n * 64 + ng * 16 + (lane & 7) + ((lane >> 4) & 1) * 8;
                int ncol = ki * 16 + ((lane >> 3) & 1) * 8;
                uint32_t bd = sbase + B2_HI + (uint32_t)(nrow * LDA + ncol) * 2;
                uint32_t bh[4], bl[4];
                ldsm4(bh, bd);
                ldsm4(bl, bd + B2_PLANE);
                #pragma unroll
                for (int mi = 0; mi < 2; mi++) {
                    mma_bf(acc[mi][2 * ng],     a_h[mi], bh);
                    mma_bf(acc[mi][2 * ng],     a_h[mi], bl);
                    mma_bf(acc[mi][2 * ng],     a_l[mi], bh);
                    mma_bf(acc[mi][2 * ng + 1], a_h[mi], bh + 2);
                    mma_bf(acc[mi][2 * ng + 1], a_h[mi], bl + 2);
                    mma_bf(acc[mi][2 * ng + 1], a_l[mi], bh + 2);
                }
            }
        }

        if (kc == 15) {
            #pragma unroll
            for (int mi = 0; mi < 2; mi++) {
                int r0 = n0 + warp_m * 32 + mi * 16 + gID;
                float rv0 = g_rinv[r0];
                float rv1 = g_rinv[r0 + 8];
                #pragma unroll
                for (int ni = 0; ni < 8; ni++) {
                    acc[mi][ni][0] *= rv0;
                    acc[mi][ni][1] *= rv0;
                    acc[mi][ni][2] *= rv1;
                    acc[mi][ni][3] *= rv1;
                }
            }
        }
    }

    __syncthreads();

    // stage transposed: Ts[o][n], o in 0..255, stride 132
    #pragma unroll
    for (int mi = 0; mi < 2; mi++)
        #pragma unroll
        for (int ni = 0; ni < 8; ni++) {
            int r0 = warp_m * 32 + mi * 16 + gID;
            int c  = warp_n * 64 + ni * 8 + t4 * 2;
            Ts[c * 132 + r0]           = acc[mi][ni][0];
            Ts[(c + 1) * 132 + r0]     = acc[mi][ni][1];
            Ts[c * 132 + r0 + 8]       = acc[mi][ni][2];
            Ts[(c + 1) * 132 + r0 + 8] = acc[mi][ni][3];
        }
    __syncthreads();
    int b = n0 >> 12, hw0 = n0 & 4095;
    float* ybase = g_yraw + (size_t)b * (256 * 4096) + hw0;
    #pragma unroll
    for (int p = 0; p < 16; p++) {
        int q = p * 512 + tid;          // 8192 float4
        int o = q >> 5, seg = q & 31;
        float4 v = *(float4*)&Ts[o * 132 + seg * 4];
        *(float4*)(ybase + (size_t)o * 4096 + seg * 4) = v;
    }
    {
        int o = tid >> 1, half = tid & 1;
        float s = 0.f, s2 = 0.f;
        #pragma unroll 16
        for (int jj = 0; jj < 64; jj++) {
            float v = Ts[o * 132 + half * 64 + jj];
            s += v; s2 += v * v;
        }
        red1[tid] = s; red2[tid] = s2;
    }
    __syncthreads();
    if (tid < 256) {
        g_sp [blockIdx.y * 256 + tid] = red1[2 * tid] + red1[2 * tid + 1];
        g_sp2[blockIdx.y * 256 + tid] = red2[2 * tid] + red2[2 * tid + 1];
    }
}

// ---------------- rinv from row partials ----------------
__global__ void k_rinv() {
    int n = blockIdx.x * 256 + threadIdx.x;
    g_rinv[n] = 1.0f / (g_rowpart[0][n] + g_rowpart[1][n] + g_rowpart[2][n] + g_rowpart[3][n]);
}

// ---------------- cinv from column partials ----------------
__global__ void k_colfin() {
    int m = threadIdx.x;   // 512 threads, 1 block
    float s = 0.f;
    #pragma unroll 8
    for (int y = 0; y < 512; y++) s += g_cp[y * 512 + m];
    g_cinv[m] = 1.0f / s;
}

// ---------------- BN statistics finalize from partials ----------------
__global__ void k_statfin() {
    int o = threadIdx.x;   // 256 threads, 1 block
    float s = 0.f, s2 = 0.f;
    #pragma unroll 8
    for (int y = 0; y < 512; y++) {
        s  += g_sp [y * 256 + o];
        s2 += g_sp2[y * 256 + o];
    }
    float mean = s * (1.0f / 65536.0f);
    float var  = s2 * (1.0f / 65536.0f) - mean * mean;
    g_mean[o] = mean;
    g_rstd[o] = rsqrtf(var + 1e-5f);
}

// ---------------- BN affine + ReLU ----------------
__global__ void k_bn(const float* __restrict__ gamma, const float* __restrict__ beta,
                     float* __restrict__ yout) {
    int idx = blockIdx.x * blockDim.x + threadIdx.x;
    size_t e0 = (size_t)idx * 4;
    int o = (int)((e0 >> 12) & 255);
    float4 v = *(const float4*)(g_yraw + e0);
    float sc = g_rstd[o] * gamma[o];
    float sh = beta[o] - g_mean[o] * sc;
    float4 r = make_float4(fmaxf(v.x * sc + sh, 0.f), fmaxf(v.y * sc + sh, 0.f),
                           fmaxf(v.z * sc + sh, 0.f), fmaxf(v.w * sc + sh, 0.f));
    *(float4*)(yout + e0) = r;
}

// ---------------- launch ----------------
extern "C" void kernel_launch(void* const* d_in, const int* in_sizes, int n_in,
                              void* d_out, int out_size) {
    const float* query = (const float*)d_in[0];
    const float* mem   = (const float*)d_in[1];
    const float* convw = (const float*)d_in[2];
    const float* gamma = (const float*)d_in[3];
    const float* beta  = (const float*)d_in[4];

    float* out = (float*)d_out;
    float* y_out   = out;
    float* ssq_out = out + 16777216;
    float* ssm_out = out + 16777216 + 33554432;

    cudaFuncSetAttribute(k_gemm1, cudaFuncAttributeMaxDynamicSharedMemorySize, SMEM1_DYN);
    cudaFuncSetAttribute(k_gemm2, cudaFuncAttributeMaxDynamicSharedMemorySize, SMEM2_DYN);

    k_norm   <<<2048, 256>>>(query);
    k_prep   <<<512, 256>>>(mem, convw);
    k_compP  <<<dim3(2, 32), 256>>>(convw);
    k_gemm1  <<<dim3(4, 512), 512, SMEM1_DYN>>>();
    k_rinv   <<<256, 256>>>();
    k_colfin <<<1, 512>>>();
    k_gemm2  <<<dim3(1, 512), 512, SMEM2_DYN>>>(ssq_out, ssm_out);
    k_statfin<<<1, 256>>>();
    k_bn     <<<16384, 256>>>(gamma, beta, y_out);
}